// round 1
// baseline (speedup 1.0000x reference)
#include <cuda_runtime.h>
#include <cuda_bf16.h>
#include <cstdint>

// Problem constants
#define B_TOTAL   8192
#define F_DIM     64
#define NX        82
#define NY        67
#define NYP       96        // padded y (multiple of 48 for warp tiling)
#define P_TOTAL   (NX * NY) // 5494
#define KPAD      192       // [hi | lo | hi] concat K
#define OUT_STRIDE (NX * NY) // per-batch output stride = 5494

// GEMM tile config
#define TILE_M    128       // batches per CTA
#define TILE_N    96        // padded y per CTA (one x per CTA)
#define ROW_PAD   200       // smem row stride in bf16 elems (400B -> LDSM conflict-free)

// Scratch (device globals; no allocation allowed)
__device__ __nv_bfloat16 g_Abf[B_TOTAL * KPAD];          // [B][192]
__device__ __nv_bfloat16 g_Wp[NX * NYP * KPAD];          // [x][96][192]

static __device__ __forceinline__ uint32_t smem_u32(const void* p) {
    return (uint32_t)__cvta_generic_to_shared(p);
}

// ---------------- Prep kernels: f32 -> bf16 hi/lo split with K-concat ----------------
__global__ void prep_A_kernel(const float* __restrict__ in) {
    int idx = blockIdx.x * blockDim.x + threadIdx.x;
    if (idx >= B_TOTAL * F_DIM) return;
    int b = idx / F_DIM;
    int k = idx - b * F_DIM;
    float v = in[idx];
    __nv_bfloat16 hi = __float2bfloat16(v);
    float resid = v - __bfloat162float(hi);
    __nv_bfloat16 lo = __float2bfloat16(resid);
    __nv_bfloat16* dst = g_Abf + b * KPAD;
    dst[k]        = hi;   // pairs with W hi
    dst[64 + k]   = lo;   // pairs with W hi
    dst[128 + k]  = hi;   // pairs with W lo
}

__global__ void prep_W_kernel(const float* __restrict__ W) {
    int idx = blockIdx.x * blockDim.x + threadIdx.x;
    if (idx >= NX * NYP * F_DIM) return;
    int x = idx / (NYP * F_DIM);
    int rem = idx - x * (NYP * F_DIM);
    int y = rem / F_DIM;
    int k = rem - y * F_DIM;
    __nv_bfloat16* dst = g_Wp + (x * NYP + y) * KPAD;
    if (y < NY) {
        int p = y * NX + x;
        float v = W[p * F_DIM + k];
        __nv_bfloat16 hi = __float2bfloat16(v);
        float resid = v - __bfloat162float(hi);
        __nv_bfloat16 lo = __float2bfloat16(resid);
        dst[k]       = hi;
        dst[64 + k]  = hi;
        dst[128 + k] = lo;
    } else {
        __nv_bfloat16 z = __float2bfloat16(0.0f);
        dst[k] = z; dst[64 + k] = z; dst[128 + k] = z;
    }
}

// ---------------- GEMM kernel: mma.sync bf16, fp32 accum ----------------
// Grid: (x = 0..81, btile = 0..B/128-1). Block: 256 threads (8 warps, 4x2 warp grid).
// Each warp: 32(M) x 48(N) tile = 2 m-frags x 6 n-frags.
__global__ __launch_bounds__(256, 2)
void gemm_kernel(const float* __restrict__ bias, float* __restrict__ out) {
    extern __shared__ __align__(16) char smem_raw[];
    __nv_bfloat16* As = (__nv_bfloat16*)smem_raw;                       // [128][ROW_PAD]
    __nv_bfloat16* Ws = As + TILE_M * ROW_PAD;                          // [96][ROW_PAD]

    const int x  = blockIdx.x;
    const int bt = blockIdx.y;
    const int tid = threadIdx.x;
    const int warp = tid >> 5;
    const int lane = tid & 31;
    const int warpM = warp & 3;   // 0..3
    const int warpN = warp >> 2;  // 0..1

    // ---- Load A tile [128][192] (int4 = 8 bf16 chunks) ----
    {
        const int4* src = (const int4*)(g_Abf + (size_t)bt * TILE_M * KPAD);
        // rows of 24 int4 each
        #pragma unroll 4
        for (int i = tid; i < TILE_M * 24; i += 256) {
            int r = i / 24;
            int c = i - r * 24;
            *(int4*)(As + r * ROW_PAD + c * 8) = src[r * 24 + c];
        }
    }
    // ---- Load W tile [96][192] ----
    {
        const int4* src = (const int4*)(g_Wp + (size_t)x * NYP * KPAD);
        #pragma unroll 2
        for (int i = tid; i < TILE_N * 24; i += 256) {
            int r = i / 24;
            int c = i - r * 24;
            *(int4*)(Ws + r * ROW_PAD + c * 8) = src[r * 24 + c];
        }
    }
    __syncthreads();

    // ---- Fragment base addresses for ldmatrix ----
    // addr(t): rows base + (lane&15), k-half = (lane>>4)*8
    uint32_t a_base = smem_u32(As + (warpM * 32 + (lane & 15)) * ROW_PAD + (lane >> 4) * 8);
    uint32_t b_base = smem_u32(Ws + (warpN * 48 + (lane & 15)) * ROW_PAD + (lane >> 4) * 8);
    const uint32_t MF_STRIDE = 16 * ROW_PAD * 2;  // +16 rows, bytes
    const uint32_t NG_STRIDE = 16 * ROW_PAD * 2;  // +16 n-rows, bytes

    float d[2][6][4];
    #pragma unroll
    for (int mf = 0; mf < 2; mf++)
        #pragma unroll
        for (int nf = 0; nf < 6; nf++)
            #pragma unroll
            for (int j = 0; j < 4; j++) d[mf][nf][j] = 0.0f;

    #pragma unroll
    for (int ks = 0; ks < KPAD / 16; ks++) {
        const uint32_t koff = ks * 32;  // 16 bf16 = 32 bytes

        uint32_t a[2][4];
        #pragma unroll
        for (int mf = 0; mf < 2; mf++) {
            asm volatile("ldmatrix.sync.aligned.m8n8.x4.shared.b16 {%0,%1,%2,%3}, [%4];"
                         : "=r"(a[mf][0]), "=r"(a[mf][1]), "=r"(a[mf][2]), "=r"(a[mf][3])
                         : "r"(a_base + mf * MF_STRIDE + koff));
        }
        uint32_t bfr[3][4];  // group g covers n16 = 2 n8-frags: regs {f0.b0, f1.b0, f0.b1, f1.b1}
        #pragma unroll
        for (int g = 0; g < 3; g++) {
            asm volatile("ldmatrix.sync.aligned.m8n8.x4.shared.b16 {%0,%1,%2,%3}, [%4];"
                         : "=r"(bfr[g][0]), "=r"(bfr[g][1]), "=r"(bfr[g][2]), "=r"(bfr[g][3])
                         : "r"(b_base + g * NG_STRIDE + koff));
        }

        #pragma unroll
        for (int mf = 0; mf < 2; mf++) {
            #pragma unroll
            for (int g = 0; g < 3; g++) {
                #pragma unroll
                for (int h = 0; h < 2; h++) {
                    float* dd = d[mf][g * 2 + h];
                    asm volatile(
                        "mma.sync.aligned.m16n8k16.row.col.f32.bf16.bf16.f32 "
                        "{%0,%1,%2,%3}, {%4,%5,%6,%7}, {%8,%9}, {%0,%1,%2,%3};"
                        : "+f"(dd[0]), "+f"(dd[1]), "+f"(dd[2]), "+f"(dd[3])
                        : "r"(a[mf][0]), "r"(a[mf][1]), "r"(a[mf][2]), "r"(a[mf][3]),
                          "r"(bfr[g][h]), "r"(bfr[g][2 + h]));
                }
            }
        }
    }

    // ---- Epilogue: add bias, transposed coalesced-ish store ----
    // d-frag mapping: d0,d1 -> row lane/4, cols (lane%4)*2 + {0,1}; d2,d3 -> row lane/4+8
    const int rbase = bt * TILE_M + warpM * 32 + (lane >> 2);
    const int cbase = warpN * 48 + (lane & 3) * 2;

    #pragma unroll
    for (int mf = 0; mf < 2; mf++) {
        const int rA = rbase + mf * 16;
        const int rB = rA + 8;
        float* outA = out + (size_t)rA * OUT_STRIDE + x * NY;
        float* outB = out + (size_t)rB * OUT_STRIDE + x * NY;
        #pragma unroll
        for (int nf = 0; nf < 6; nf++) {
            const int y0 = cbase + nf * 8;
            #pragma unroll
            for (int j = 0; j < 2; j++) {
                const int y = y0 + j;
                if (y < NY) {
                    const float bb = bias[y * NX + x];
                    outA[y] = d[mf][nf][j] + bb;
                    outB[y] = d[mf][nf][2 + j] + bb;
                }
            }
        }
    }
}

// ---------------- Launch ----------------
extern "C" void kernel_launch(void* const* d_in, const int* in_sizes, int n_in,
                              void* d_out, int out_size) {
    // Defensive mapping by element count (sizes are distinct)
    const float* inputs = nullptr;  // 8192*64
    const float* W = nullptr;       // 5494*64
    const float* bias = nullptr;    // 5494
    for (int i = 0; i < n_in; i++) {
        if (in_sizes[i] == B_TOTAL * F_DIM) inputs = (const float*)d_in[i];
        else if (in_sizes[i] == P_TOTAL * F_DIM) W = (const float*)d_in[i];
        else if (in_sizes[i] == P_TOTAL) bias = (const float*)d_in[i];
    }
    float* out = (float*)d_out;

    // Prep: hi/lo bf16 split + W rearrangement
    {
        int total = B_TOTAL * F_DIM;
        prep_A_kernel<<<(total + 255) / 256, 256>>>(inputs);
    }
    {
        int total = NX * NYP * F_DIM;
        prep_W_kernel<<<(total + 255) / 256, 256>>>(W);
    }

    // GEMM
    const int smem_bytes = (TILE_M + TILE_N) * ROW_PAD * 2;  // 89600
    cudaFuncSetAttribute(gemm_kernel, cudaFuncAttributeMaxDynamicSharedMemorySize, smem_bytes);
    dim3 grid(NX, B_TOTAL / TILE_M);  // (82, 64)
    gemm_kernel<<<grid, 256, smem_bytes>>>(bias, out);
}

// round 3
// speedup vs baseline: 1.7239x; 1.7239x over previous
#include <cuda_runtime.h>
#include <cuda_fp16.h>
#include <cstdint>

// ---------------- Problem constants ----------------
#define B_TOTAL   8192
#define F_DIM     64
#define NX        82
#define NY        67
#define NYP       96
#define P_TOTAL   (NX * NY)      // 5494
#define KP        128            // [hi | lo] fp16 concat K
#define KSTEPS    (KP / 16)      // 8

// ---------------- Tile config ----------------
#define TILE_M    128
#define BT_PER_CTA 8
#define GRID_Y    (B_TOTAL / TILE_M / BT_PER_CTA)   // 8
#define ROWE      136            // smem row stride in fp16 elems (272B, conflict-free LDSM)

// SMEM layout (bytes)
#define OFF_A     0
#define A_BYTES   (TILE_M * ROWE * 2)     // 34816 (also = 128*68*4 staging, exact overlay)
#define OFF_W     A_BYTES                 // 34816
#define W_BYTES   (NYP * ROWE * 2)        // 26112
#define OFF_BIAS  (OFF_W + W_BYTES)       // 60928
#define SMEM_TOTAL (OFF_BIAS + 288)       // 61216
#define DS_STRIDE 68                      // f32 staging stride

// ---------------- Scratch (device globals; no allocation allowed) ----------------
__device__ __align__(16) __half g_Ah[B_TOTAL * KP];        // [B][128] = [hi|lo]
__device__ __align__(16) __half g_Wp[NX * NYP * KP];       // [x][96][128] = [hi|hi]

static __device__ __forceinline__ uint32_t smem_u32(const void* p) {
    return (uint32_t)__cvta_generic_to_shared(p);
}

// ---------------- Merged prep kernel ----------------
// Blocks [0, 2048): A split. Blocks [2048, 4016): W rearrange+replicate.
#define A_BLOCKS 2048
#define W_BLOCKS ((NX * NYP * F_DIM) / 256)   // 1968
__global__ void prep_kernel(const float* __restrict__ in, const float* __restrict__ W) {
    int bid = blockIdx.x;
    if (bid < A_BLOCKS) {
        int idx = bid * 256 + threadIdx.x;       // < 524288
        int b = idx >> 6;
        int k = idx & 63;
        float v = in[idx];
        __half hi = __float2half(v);
        __half lo = __float2half(v - __half2float(hi));
        g_Ah[b * KP + k]      = hi;
        g_Ah[b * KP + 64 + k] = lo;
    } else {
        int idx = (bid - A_BLOCKS) * 256 + threadIdx.x;  // < 503808
        int x = idx / (NYP * F_DIM);
        int rem = idx - x * (NYP * F_DIM);
        int y = rem >> 6;
        int k = rem & 63;
        __half hv = __float2half(0.0f);
        if (y < NY) {
            float v = W[(y * NX + x) * F_DIM + k];
            hv = __float2half(v);
        }
        g_Wp[(x * NYP + y) * KP + k]      = hv;
        g_Wp[(x * NYP + y) * KP + 64 + k] = hv;
    }
}

// ---------------- GEMM kernel: mma.sync fp16, fp32 accum, W-stationary ----------------
// Grid: (x = 0..81, by = 0..7). Block: 256 threads (8 warps, 4M x 2N).
// Each CTA: load W[x] once, loop over 8 batch tiles of 128.
__global__ __launch_bounds__(256, 2)
void gemm_kernel(const float* __restrict__ bias, float* __restrict__ out) {
    extern __shared__ __align__(16) char smem[];
    __half* As = (__half*)(smem + OFF_A);        // [128][ROWE]
    __half* Ws = (__half*)(smem + OFF_W);        // [96][ROWE]
    float* bias_s = (float*)(smem + OFF_BIAS);   // [67]
    float* Ds = (float*)(smem + OFF_A);          // staging overlay [128][68]

    const int x  = blockIdx.x;
    const int by = blockIdx.y;
    const int tid = threadIdx.x;
    const int warp = tid >> 5;
    const int lane = tid & 31;
    const int warpM = warp & 3;   // 0..3
    const int warpN = warp >> 2;  // 0..1

    // ---- Load W tile [96][128] once ----
    {
        const int4* src = (const int4*)(g_Wp + (size_t)x * NYP * KP);
        #pragma unroll
        for (int i = tid; i < NYP * (KP / 8); i += 256) {   // 1536 int4
            int r = i >> 4;
            int c = i & 15;
            *(int4*)(Ws + r * ROWE + c * 8) = src[i];
        }
    }
    if (tid < NY) bias_s[tid] = bias[tid * NX + x];

    // ldmatrix base addresses (fixed layout)
    const uint32_t a_base = smem_u32(As + (warpM * 32 + (lane & 15)) * ROWE + (lane >> 4) * 8);
    const uint32_t b_base = smem_u32(Ws + (warpN * 48 + (lane & 15)) * ROWE + (lane >> 4) * 8);
    const uint32_t MF_STRIDE = 16 * ROWE * 2;
    const uint32_t NG_STRIDE = 16 * ROWE * 2;

    // d-frag output coordinates
    const int r0 = warpM * 32 + (lane >> 2);
    const int cb = warpN * 48 + (lane & 3) * 2;

    for (int t = 0; t < BT_PER_CTA; t++) {
        const int bt = by * BT_PER_CTA + t;

        // ---- Load A tile [128][128] ----
        {
            const int4* src = (const int4*)(g_Ah + (size_t)bt * TILE_M * KP);
            #pragma unroll
            for (int i = tid; i < TILE_M * (KP / 8); i += 256) {  // 2048 int4
                int r = i >> 4;
                int c = i & 15;
                *(int4*)(As + r * ROWE + c * 8) = src[i];
            }
        }
        __syncthreads();

        float d[2][6][4];
        #pragma unroll
        for (int mf = 0; mf < 2; mf++)
            #pragma unroll
            for (int nf = 0; nf < 6; nf++)
                #pragma unroll
                for (int j = 0; j < 4; j++) d[mf][nf][j] = 0.0f;

        #pragma unroll
        for (int ks = 0; ks < KSTEPS; ks++) {
            const uint32_t koff = ks * 32;  // 16 fp16 = 32 bytes

            uint32_t a[2][4];
            #pragma unroll
            for (int mf = 0; mf < 2; mf++) {
                asm volatile("ldmatrix.sync.aligned.m8n8.x4.shared.b16 {%0,%1,%2,%3}, [%4];"
                             : "=r"(a[mf][0]), "=r"(a[mf][1]), "=r"(a[mf][2]), "=r"(a[mf][3])
                             : "r"(a_base + mf * MF_STRIDE + koff));
            }
            uint32_t bfr[3][4];
            #pragma unroll
            for (int g = 0; g < 3; g++) {
                asm volatile("ldmatrix.sync.aligned.m8n8.x4.shared.b16 {%0,%1,%2,%3}, [%4];"
                             : "=r"(bfr[g][0]), "=r"(bfr[g][1]), "=r"(bfr[g][2]), "=r"(bfr[g][3])
                             : "r"(b_base + g * NG_STRIDE + koff));
            }

            #pragma unroll
            for (int mf = 0; mf < 2; mf++) {
                #pragma unroll
                for (int g = 0; g < 3; g++) {
                    #pragma unroll
                    for (int h = 0; h < 2; h++) {
                        float* dd = d[mf][g * 2 + h];
                        asm volatile(
                            "mma.sync.aligned.m16n8k16.row.col.f32.f16.f16.f32 "
                            "{%0,%1,%2,%3}, {%4,%5,%6,%7}, {%8,%9}, {%0,%1,%2,%3};"
                            : "+f"(dd[0]), "+f"(dd[1]), "+f"(dd[2]), "+f"(dd[3])
                            : "r"(a[mf][0]), "r"(a[mf][1]), "r"(a[mf][2]), "r"(a[mf][3]),
                              "r"(bfr[g][h]), "r"(bfr[g][2 + h]));
                    }
                }
            }
        }
        __syncthreads();   // all warps done reading As before staging overwrites it

        // ---- Stage to SMEM (transpose to row-major [128][67]) ----
        #pragma unroll
        for (int mf = 0; mf < 2; mf++) {
            const int rA = r0 + mf * 16;
            #pragma unroll
            for (int nf = 0; nf < 6; nf++) {
                #pragma unroll
                for (int j = 0; j < 2; j++) {
                    const int y = cb + nf * 8 + j;
                    if (y < NY) {
                        Ds[rA * DS_STRIDE + y]       = d[mf][nf][j];
                        Ds[(rA + 8) * DS_STRIDE + y] = d[mf][nf][2 + j];
                    }
                }
            }
        }
        __syncthreads();

        // ---- Coalesced stores with bias ----
        float* outp = out + (size_t)(bt * TILE_M) * P_TOTAL + x * NY;
        #pragma unroll 4
        for (int i = tid; i < TILE_M * NY; i += 256) {
            int r = i / NY;
            int y = i - r * NY;
            outp[(size_t)r * P_TOTAL + y] = Ds[r * DS_STRIDE + y] + bias_s[y];
        }
        __syncthreads();   // staging/As free before next A load
    }
}

// ---------------- Launch ----------------
extern "C" void kernel_launch(void* const* d_in, const int* in_sizes, int n_in,
                              void* d_out, int out_size) {
    const float* inputs = nullptr;  // 8192*64
    const float* W = nullptr;       // 5494*64
    const float* bias = nullptr;    // 5494
    for (int i = 0; i < n_in; i++) {
        if (in_sizes[i] == B_TOTAL * F_DIM) inputs = (const float*)d_in[i];
        else if (in_sizes[i] == P_TOTAL * F_DIM) W = (const float*)d_in[i];
        else if (in_sizes[i] == P_TOTAL) bias = (const float*)d_in[i];
    }
    float* out = (float*)d_out;

    prep_kernel<<<A_BLOCKS + W_BLOCKS, 256>>>(inputs, W);

    cudaFuncSetAttribute(gemm_kernel, cudaFuncAttributeMaxDynamicSharedMemorySize, SMEM_TOTAL);
    dim3 grid(NX, GRID_Y);   // (82, 8)
    gemm_kernel<<<grid, 256, SMEM_TOTAL>>>(bias, out);
}

// round 4
// speedup vs baseline: 2.4684x; 1.4319x over previous
#include <cuda_runtime.h>
#include <cuda_fp16.h>
#include <cstdint>

// ---------------- Problem constants ----------------
#define B_TOTAL   8192
#define F_DIM     64
#define NX        82
#define NY        67
#define NYP       96
#define P_TOTAL   (NX * NY)      // 5494
#define KP        64             // plain fp16 K
#define KSTEPS    (KP / 16)      // 4

// ---------------- Tile config ----------------
#define TILE_M    128
#define BT_PER_CTA 8
#define GRID_Y    (B_TOTAL / TILE_M / BT_PER_CTA)   // 8
#define ROWE      72             // smem row stride in fp16 (144B = 9*16B, LDSM conflict-free)

// SMEM layout (bytes)
#define OFF_A     0
#define STAGE_BYTES (TILE_M * 68 * 4)           // 34816 staging overlay (>= A tile 18432)
#define OFF_W     STAGE_BYTES                   // 34816
#define W_BYTES   (NYP * ROWE * 2)              // 13824
#define OFF_BIAS  (OFF_W + W_BYTES)             // 48640
#define SMEM_TOTAL (OFF_BIAS + 288)             // 48928
#define DS_STRIDE 68

// ---------------- Scratch (device globals; no allocation allowed) ----------------
__device__ __align__(16) __half g_Ah[B_TOTAL * KP];        // [B][64] fp16
__device__ __align__(16) __half g_Wp[NX * NYP * KP];       // [x][96][64] fp16

static __device__ __forceinline__ uint32_t smem_u32(const void* p) {
    return (uint32_t)__cvta_generic_to_shared(p);
}
static __device__ __forceinline__ void cp_async16(uint32_t dst, const void* src) {
    asm volatile("cp.async.cg.shared.global [%0], [%1], 16;" :: "r"(dst), "l"(src));
}

// ---------------- Merged prep kernel (single launch) ----------------
// idx < B*16: A fp32->fp16 (float4 -> 4 halves). Else: W rearrange [p][64] -> [x][96][64].
#define A_CHUNKS (B_TOTAL * 16)          // 131072
#define W_CHUNKS (NX * NYP * 16)         // 125952
#define PREP_BLOCKS ((A_CHUNKS + W_CHUNKS) / 256)   // 1004
__global__ void prep_kernel(const float* __restrict__ in, const float* __restrict__ W) {
    int idx = blockIdx.x * 256 + threadIdx.x;
    if (idx < A_CHUNKS) {
        float4 v = ((const float4*)in)[idx];
        __half2 h0 = __floats2half2_rn(v.x, v.y);
        __half2 h1 = __floats2half2_rn(v.z, v.w);
        uint2 pack = { *(uint32_t*)&h0, *(uint32_t*)&h1 };
        ((uint2*)g_Ah)[idx] = pack;
    } else {
        int j = idx - A_CHUNKS;
        int x = j / (NYP * 16);
        int rem = j - x * (NYP * 16);
        int y = rem >> 4;
        int c4 = rem & 15;
        uint2 pack = {0u, 0u};
        if (y < NY) {
            float4 v = *(const float4*)(W + ((size_t)(y * NX + x) * F_DIM + c4 * 4));
            __half2 h0 = __floats2half2_rn(v.x, v.y);
            __half2 h1 = __floats2half2_rn(v.z, v.w);
            pack.x = *(uint32_t*)&h0;
            pack.y = *(uint32_t*)&h1;
        }
        *(uint2*)(g_Wp + ((size_t)(x * NYP + y) * KP + c4 * 4)) = pack;
    }
}

// ---------------- GEMM kernel: mma.sync fp16, fp32 accum, W-stationary ----------------
// Grid: (x = 0..81, by = 0..7). Block: 256 threads (8 warps, 4M x 2N).
__global__ __launch_bounds__(256, 3)
void gemm_kernel(const float* __restrict__ bias, float* __restrict__ out) {
    extern __shared__ __align__(16) char smem[];
    __half* As = (__half*)(smem + OFF_A);        // [128][72]
    __half* Ws = (__half*)(smem + OFF_W);        // [96][72]
    float* bias_s = (float*)(smem + OFF_BIAS);   // [67]
    float* Ds = (float*)(smem + OFF_A);          // staging overlay [128][68]

    const int x  = blockIdx.x;
    const int by = blockIdx.y;
    const int tid = threadIdx.x;
    const int warp = tid >> 5;
    const int lane = tid & 31;
    const int warpM = warp & 3;   // 0..3
    const int warpN = warp >> 2;  // 0..1
    const uint32_t sbase = smem_u32(smem);

    // ---- Load W tile [96][64] once (cp.async) ----
    {
        const char* src = (const char*)(g_Wp + (size_t)x * NYP * KP);
        #pragma unroll
        for (int i = tid; i < NYP * 8; i += 256) {   // 768 chunks, 3/thread
            int r = i >> 3;
            int c = i & 7;
            cp_async16(sbase + OFF_W + (r * ROWE + c * 8) * 2, src + (r * KP + c * 8) * 2);
        }
    }
    if (tid < NY) bias_s[tid] = bias[tid * NX + x];

    // ldmatrix base addresses
    const uint32_t a_base = smem_u32(As + (warpM * 32 + (lane & 15)) * ROWE + (lane >> 4) * 8);
    const uint32_t b_base = smem_u32(Ws + (warpN * 48 + (lane & 15)) * ROWE + (lane >> 4) * 8);
    const uint32_t MF_STRIDE = 16 * ROWE * 2;
    const uint32_t NG_STRIDE = 16 * ROWE * 2;

    // d-frag output coordinates
    const int r0 = warpM * 32 + (lane >> 2);
    const int cb = warpN * 48 + (lane & 3) * 2;

    for (int t = 0; t < BT_PER_CTA; t++) {
        const int bt = by * BT_PER_CTA + t;

        // ---- Load A tile [128][64] via cp.async ----
        {
            const char* src = (const char*)(g_Ah + (size_t)bt * TILE_M * KP);
            #pragma unroll
            for (int i = tid; i < TILE_M * 8; i += 256) {  // 1024 chunks, 4/thread
                int r = i >> 3;
                int c = i & 7;
                cp_async16(sbase + OFF_A + (r * ROWE + c * 8) * 2, src + (r * KP + c * 8) * 2);
            }
        }
        asm volatile("cp.async.commit_group;\n\tcp.async.wait_group 0;" ::: "memory");
        __syncthreads();

        float d[2][6][4];
        #pragma unroll
        for (int mf = 0; mf < 2; mf++)
            #pragma unroll
            for (int nf = 0; nf < 6; nf++)
                #pragma unroll
                for (int j = 0; j < 4; j++) d[mf][nf][j] = 0.0f;

        #pragma unroll
        for (int ks = 0; ks < KSTEPS; ks++) {
            const uint32_t koff = ks * 32;  // 16 fp16 = 32 bytes

            uint32_t a[2][4];
            #pragma unroll
            for (int mf = 0; mf < 2; mf++) {
                asm volatile("ldmatrix.sync.aligned.m8n8.x4.shared.b16 {%0,%1,%2,%3}, [%4];"
                             : "=r"(a[mf][0]), "=r"(a[mf][1]), "=r"(a[mf][2]), "=r"(a[mf][3])
                             : "r"(a_base + mf * MF_STRIDE + koff));
            }
            uint32_t bfr[3][4];
            #pragma unroll
            for (int g = 0; g < 3; g++) {
                asm volatile("ldmatrix.sync.aligned.m8n8.x4.shared.b16 {%0,%1,%2,%3}, [%4];"
                             : "=r"(bfr[g][0]), "=r"(bfr[g][1]), "=r"(bfr[g][2]), "=r"(bfr[g][3])
                             : "r"(b_base + g * NG_STRIDE + koff));
            }

            #pragma unroll
            for (int mf = 0; mf < 2; mf++) {
                #pragma unroll
                for (int g = 0; g < 3; g++) {
                    #pragma unroll
                    for (int h = 0; h < 2; h++) {
                        float* dd = d[mf][g * 2 + h];
                        asm volatile(
                            "mma.sync.aligned.m16n8k16.row.col.f32.f16.f16.f32 "
                            "{%0,%1,%2,%3}, {%4,%5,%6,%7}, {%8,%9}, {%0,%1,%2,%3};"
                            : "+f"(dd[0]), "+f"(dd[1]), "+f"(dd[2]), "+f"(dd[3])
                            : "r"(a[mf][0]), "r"(a[mf][1]), "r"(a[mf][2]), "r"(a[mf][3]),
                              "r"(bfr[g][h]), "r"(bfr[g][2 + h]));
                    }
                }
            }
        }
        __syncthreads();   // all warps done reading As before staging overwrites it

        // ---- Stage to SMEM (transpose to row-major [128][67]), float2 stores ----
        #pragma unroll
        for (int mf = 0; mf < 2; mf++) {
            const int rA = r0 + mf * 16;
            #pragma unroll
            for (int nf = 0; nf < 6; nf++) {
                const int y = cb + nf * 8;   // even
                if (y + 1 < NY) {
                    float2 v0 = make_float2(d[mf][nf][0], d[mf][nf][1]);
                    float2 v1 = make_float2(d[mf][nf][2], d[mf][nf][3]);
                    *(float2*)&Ds[rA * DS_STRIDE + y]       = v0;
                    *(float2*)&Ds[(rA + 8) * DS_STRIDE + y] = v1;
                } else if (y < NY) {
                    Ds[rA * DS_STRIDE + y]       = d[mf][nf][0];
                    Ds[(rA + 8) * DS_STRIDE + y] = d[mf][nf][2];
                }
            }
        }
        __syncthreads();

        // ---- Coalesced stores with bias ----
        float* outp = out + (size_t)(bt * TILE_M) * P_TOTAL + x * NY;
        #pragma unroll 4
        for (int i = tid; i < TILE_M * NY; i += 256) {
            int r = i / NY;
            int y = i - r * NY;
            outp[(size_t)r * P_TOTAL + y] = Ds[r * DS_STRIDE + y] + bias_s[y];
        }
        __syncthreads();   // staging region free before next A load
    }
}

// ---------------- Launch ----------------
extern "C" void kernel_launch(void* const* d_in, const int* in_sizes, int n_in,
                              void* d_out, int out_size) {
    const float* inputs = nullptr;  // 8192*64
    const float* W = nullptr;       // 5494*64
    const float* bias = nullptr;    // 5494
    for (int i = 0; i < n_in; i++) {
        if (in_sizes[i] == B_TOTAL * F_DIM) inputs = (const float*)d_in[i];
        else if (in_sizes[i] == P_TOTAL * F_DIM) W = (const float*)d_in[i];
        else if (in_sizes[i] == P_TOTAL) bias = (const float*)d_in[i];
    }
    float* out = (float*)d_out;

    prep_kernel<<<PREP_BLOCKS, 256>>>(inputs, W);

    cudaFuncSetAttribute(gemm_kernel, cudaFuncAttributeMaxDynamicSharedMemorySize, SMEM_TOTAL);
    dim3 grid(NX, GRID_Y);   // (82, 8)
    gemm_kernel<<<grid, 256, SMEM_TOTAL>>>(bias, out);
}

// round 5
// speedup vs baseline: 2.9234x; 1.1843x over previous
#include <cuda_runtime.h>
#include <cuda_fp16.h>
#include <cstdint>

// ---------------- Problem constants ----------------
#define B_TOTAL   8192
#define F_DIM     64
#define NX        82
#define NY        67
#define NYP       96
#define P_TOTAL   (NX * NY)      // 5494
#define KP        64             // fp16 K
#define KSTEPS    (KP / 16)      // 4

// ---------------- Tile config ----------------
#define TILE_M    128
#define BT_PER_CTA 4
#define GRID_Y    (B_TOTAL / TILE_M / BT_PER_CTA)   // 16
#define ROWE      72             // smem row stride in fp16 (144B = 9*16B)

// SMEM layout (bytes)
#define OFF_A     0
#define A_BYTES   (TILE_M * ROWE * 2)     // 18432
#define OFF_W     A_BYTES                 // 18432
#define W_BYTES   (NYP * ROWE * 2)        // 13824
#define OFF_DS    (OFF_W + W_BYTES)       // 32256
#define DS_STRIDE 68
#define DS_BYTES  (TILE_M * DS_STRIDE * 4)  // 34816
#define OFF_BIAS  (OFF_DS + DS_BYTES)     // 67072
#define SMEM_TOTAL (OFF_BIAS + 384)       // 67456  -> 3 CTAs/SM

// ---------------- Scratch (device globals; no allocation allowed) ----------------
__device__ __align__(16) __half g_Ah[B_TOTAL * KP];        // [B][64] fp16
__device__ __align__(16) __half g_Wp[NX * NYP * KP];       // [x][96][64] fp16

static __device__ __forceinline__ uint32_t smem_u32(const void* p) {
    return (uint32_t)__cvta_generic_to_shared(p);
}
static __device__ __forceinline__ void cp_async16(uint32_t dst, const void* src) {
    asm volatile("cp.async.cg.shared.global [%0], [%1], 16;" :: "r"(dst), "l"(src));
}

// ---------------- Merged prep kernel (single launch) ----------------
#define A_CHUNKS (B_TOTAL * 16)          // 131072
#define W_CHUNKS (NX * NYP * 16)         // 125952
#define PREP_BLOCKS ((A_CHUNKS + W_CHUNKS) / 256)   // 1004
__global__ void prep_kernel(const float* __restrict__ in, const float* __restrict__ W) {
    int idx = blockIdx.x * 256 + threadIdx.x;
    if (idx < A_CHUNKS) {
        float4 v = ((const float4*)in)[idx];
        __half2 h0 = __floats2half2_rn(v.x, v.y);
        __half2 h1 = __floats2half2_rn(v.z, v.w);
        uint2 pack = { *(uint32_t*)&h0, *(uint32_t*)&h1 };
        ((uint2*)g_Ah)[idx] = pack;
    } else {
        int j = idx - A_CHUNKS;
        int x = j / (NYP * 16);
        int rem = j - x * (NYP * 16);
        int y = rem >> 4;
        int c4 = rem & 15;
        uint2 pack = {0u, 0u};
        if (y < NY) {
            float4 v = *(const float4*)(W + ((size_t)(y * NX + x) * F_DIM + c4 * 4));
            __half2 h0 = __floats2half2_rn(v.x, v.y);
            __half2 h1 = __floats2half2_rn(v.z, v.w);
            pack.x = *(uint32_t*)&h0;
            pack.y = *(uint32_t*)&h1;
        }
        *(uint2*)(g_Wp + ((size_t)(x * NYP + y) * KP + c4 * 4)) = pack;
    }
}

// ---------------- GEMM kernel ----------------
// Grid: (x = 0..81, by = 0..15). Block: 256 threads (8 warps, 4M x 2N).
__global__ __launch_bounds__(256, 3)
void gemm_kernel(const float* __restrict__ bias, float* __restrict__ out) {
    extern __shared__ __align__(16) char smem[];
    __half* As = (__half*)(smem + OFF_A);        // [128][72]
    __half* Ws = (__half*)(smem + OFF_W);        // [96][72]
    float* Ds = (float*)(smem + OFF_DS);         // [128][68] staging
    float* bias_s = (float*)(smem + OFF_BIAS);   // [96], zero-padded

    const int x  = blockIdx.x;
    const int by = blockIdx.y;
    const int tid = threadIdx.x;
    const int lane = tid & 31;
    const int warp = tid >> 5;
    const int warpM = warp & 3;   // 0..3
    const int warpN = warp >> 2;  // 0..1
    const uint32_t sbase = smem_u32(smem);

    // ---- Prologue: W tile + first A tile + bias (one cp.async group) ----
    {
        const char* srcW = (const char*)(g_Wp + (size_t)x * NYP * KP);
        #pragma unroll
        for (int i = tid; i < NYP * 8; i += 256) {
            int r = i >> 3;
            int c = i & 7;
            cp_async16(sbase + OFF_W + r * 144 + c * 16, srcW + r * 128 + c * 16);
        }
        const char* srcA = (const char*)(g_Ah + (size_t)(by * BT_PER_CTA) * TILE_M * KP);
        #pragma unroll
        for (int i = tid; i < TILE_M * 8; i += 256) {
            int r = i >> 3;
            int c = i & 7;
            cp_async16(sbase + OFF_A + r * 144 + c * 16, srcA + r * 128 + c * 16);
        }
        asm volatile("cp.async.commit_group;" ::: "memory");
    }
    if (tid < NYP) bias_s[tid] = (tid < NY) ? bias[tid * NX + x] : 0.0f;

    // ldmatrix base addresses (fixed across tiles)
    const uint32_t a_base = smem_u32(As + (warpM * 32 + (lane & 15)) * ROWE + (lane >> 4) * 8);
    const uint32_t b_base = smem_u32(Ws + (warpN * 48 + (lane & 15)) * ROWE + (lane >> 4) * 8);
    const uint32_t MF_STRIDE = 16 * ROWE * 2;
    const uint32_t NG_STRIDE = 16 * ROWE * 2;

    // d-frag output coordinates
    const int r0 = warpM * 32 + (lane >> 2);
    const int cb = warpN * 48 + (lane & 3) * 2;

    // writeout walker init (division once)
    const int w_r0 = tid / NY;
    const int w_y0 = tid - w_r0 * NY;

    for (int t = 0; t < BT_PER_CTA; t++) {
        const int bt = by * BT_PER_CTA + t;

        asm volatile("cp.async.wait_group 0;" ::: "memory");
        __syncthreads();   // A[t] (and W on t=0) visible to all

        float d[2][6][4];
        #pragma unroll
        for (int mf = 0; mf < 2; mf++)
            #pragma unroll
            for (int nf = 0; nf < 6; nf++)
                #pragma unroll
                for (int j = 0; j < 4; j++) d[mf][nf][j] = 0.0f;

        #pragma unroll
        for (int ks = 0; ks < KSTEPS; ks++) {
            const uint32_t koff = ks * 32;

            uint32_t a[2][4];
            #pragma unroll
            for (int mf = 0; mf < 2; mf++) {
                asm volatile("ldmatrix.sync.aligned.m8n8.x4.shared.b16 {%0,%1,%2,%3}, [%4];"
                             : "=r"(a[mf][0]), "=r"(a[mf][1]), "=r"(a[mf][2]), "=r"(a[mf][3])
                             : "r"(a_base + mf * MF_STRIDE + koff));
            }
            uint32_t bfr[3][4];
            #pragma unroll
            for (int g = 0; g < 3; g++) {
                asm volatile("ldmatrix.sync.aligned.m8n8.x4.shared.b16 {%0,%1,%2,%3}, [%4];"
                             : "=r"(bfr[g][0]), "=r"(bfr[g][1]), "=r"(bfr[g][2]), "=r"(bfr[g][3])
                             : "r"(b_base + g * NG_STRIDE + koff));
            }

            #pragma unroll
            for (int mf = 0; mf < 2; mf++) {
                #pragma unroll
                for (int g = 0; g < 3; g++) {
                    #pragma unroll
                    for (int h = 0; h < 2; h++) {
                        float* dd = d[mf][g * 2 + h];
                        asm volatile(
                            "mma.sync.aligned.m16n8k16.row.col.f32.f16.f16.f32 "
                            "{%0,%1,%2,%3}, {%4,%5,%6,%7}, {%8,%9}, {%0,%1,%2,%3};"
                            : "+f"(dd[0]), "+f"(dd[1]), "+f"(dd[2]), "+f"(dd[3])
                            : "r"(a[mf][0]), "r"(a[mf][1]), "r"(a[mf][2]), "r"(a[mf][3]),
                              "r"(bfr[g][h]), "r"(bfr[g][2 + h]));
                    }
                }
            }
        }
        __syncthreads();   // all warps done reading As

        // ---- Prefetch next A tile (overlaps entire epilogue) ----
        if (t + 1 < BT_PER_CTA) {
            const char* srcA = (const char*)(g_Ah + (size_t)(bt + 1) * TILE_M * KP);
            #pragma unroll
            for (int i = tid; i < TILE_M * 8; i += 256) {
                int r = i >> 3;
                int c = i & 7;
                cp_async16(sbase + OFF_A + r * 144 + c * 16, srcA + r * 128 + c * 16);
            }
            asm volatile("cp.async.commit_group;" ::: "memory");
        }

        // ---- Stage to SMEM with bias folded (float2 stores) ----
        #pragma unroll
        for (int nf = 0; nf < 6; nf++) {
            const int y = cb + nf * 8;   // even
            const float b0 = bias_s[y];
            const float b1 = bias_s[y + 1];
            #pragma unroll
            for (int mf = 0; mf < 2; mf++) {
                const int rA = r0 + mf * 16;
                if (y + 1 < NY) {
                    float2 v0 = make_float2(d[mf][nf][0] + b0, d[mf][nf][1] + b1);
                    float2 v1 = make_float2(d[mf][nf][2] + b0, d[mf][nf][3] + b1);
                    *(float2*)&Ds[rA * DS_STRIDE + y]       = v0;
                    *(float2*)&Ds[(rA + 8) * DS_STRIDE + y] = v1;
                } else if (y < NY) {
                    Ds[rA * DS_STRIDE + y]       = d[mf][nf][0] + b0;
                    Ds[(rA + 8) * DS_STRIDE + y] = d[mf][nf][2] + b0;
                }
            }
        }
        __syncthreads();

        // ---- Coalesced writeout, division-free walker ----
        {
            float* outp = out + (size_t)(bt * TILE_M) * P_TOTAL + x * NY;
            int y = w_y0;
            int offG = w_r0 * P_TOTAL + w_y0;
            int offS = w_r0 * DS_STRIDE + w_y0;
            #pragma unroll 4
            for (int i = tid; i < TILE_M * NY; i += 256) {
                outp[offG] = Ds[offS];
                y += 55; offG += 3 * P_TOTAL + 55; offS += 3 * DS_STRIDE + 55;
                if (y >= NY) { y -= NY; offG += P_TOTAL - NY; offS += DS_STRIDE - NY; }
            }
        }
        __syncthreads();   // Ds free; next iter waits its A prefetch
    }
}

// ---------------- Launch ----------------
extern "C" void kernel_launch(void* const* d_in, const int* in_sizes, int n_in,
                              void* d_out, int out_size) {
    const float* inputs = nullptr;  // 8192*64
    const float* W = nullptr;       // 5494*64
    const float* bias = nullptr;    // 5494
    for (int i = 0; i < n_in; i++) {
        if (in_sizes[i] == B_TOTAL * F_DIM) inputs = (const float*)d_in[i];
        else if (in_sizes[i] == P_TOTAL * F_DIM) W = (const float*)d_in[i];
        else if (in_sizes[i] == P_TOTAL) bias = (const float*)d_in[i];
    }
    float* out = (float*)d_out;

    prep_kernel<<<PREP_BLOCKS, 256>>>(inputs, W);

    cudaFuncSetAttribute(gemm_kernel, cudaFuncAttributeMaxDynamicSharedMemorySize, SMEM_TOTAL);
    dim3 grid(NX, GRID_Y);   // (82, 16)
    gemm_kernel<<<grid, 256, SMEM_TOTAL>>>(bias, out);
}

// round 6
// speedup vs baseline: 3.0317x; 1.0371x over previous
#include <cuda_runtime.h>
#include <cuda_fp16.h>
#include <cstdint>

// ---------------- Problem constants ----------------
#define B_TOTAL   8192
#define F_DIM     64
#define NX        82
#define NY        67
#define NYP       96
#define P_TOTAL   (NX * NY)      // 5494
#define KP        64             // fp16 K
#define KSTEPS    (KP / 16)      // 4

// ---------------- Tile config ----------------
#define TILE_M    128
#define BT_PER_CTA 4
#define GRID_Y    (B_TOTAL / TILE_M / BT_PER_CTA)   // 16
#define ROWE      72             // W smem row stride in fp16 (144B)

// SMEM layout (bytes)
#define OFF_W     0
#define W_BYTES   (NYP * ROWE * 2)          // 13824
#define OFF_DS    W_BYTES                   // 13824
#define DS_STRIDE 68
#define DS_BYTES  (TILE_M * DS_STRIDE * 4)  // 34816
#define OFF_BIAS  (OFF_DS + DS_BYTES)       // 48640
#define SMEM_TOTAL (OFF_BIAS + 384)         // 49024  -> 3 CTAs/SM

// ---------------- Scratch (device globals; no allocation allowed) ----------------
// A in mma fragment order: [bt][warpM][ks][mf][lane] of uint4 (16B per lane-slot)
#define AFRAG_U4  (B_TOTAL * KP * 2 / 16)   // 65536 uint4
__device__ __align__(16) uint4 g_Afrag[AFRAG_U4];
__device__ __align__(16) __half g_Wp[NX * NYP * KP];   // [x][96][64]

static __device__ __forceinline__ uint32_t smem_u32(const void* p) {
    return (uint32_t)__cvta_generic_to_shared(p);
}
static __device__ __forceinline__ void cp_async16(uint32_t dst, const void* src) {
    asm volatile("cp.async.cg.shared.global [%0], [%1], 16;" :: "r"(dst), "l"(src));
}
static __device__ __forceinline__ uint32_t packh2(float a, float b) {
    __half2 h = __floats2half2_rn(a, b);
    return *(uint32_t*)&h;
}

// ---------------- Merged prep kernel ----------------
// idx < AFRAG_U4: build one A-fragment 16B chunk. Else: W rearrange (uint2 = 4 halves).
#define W_CHUNKS (NX * NYP * 16)                 // 125952
#define PREP_THREADS (AFRAG_U4 + W_CHUNKS)       // 191488
#define PREP_BLOCKS ((PREP_THREADS + 255) / 256) // 749
__global__ void prep_kernel(const float* __restrict__ in, const float* __restrict__ W) {
    int idx = blockIdx.x * 256 + threadIdx.x;
    if (idx < AFRAG_U4) {
        // decompose: [bt(6b)][ws(2)][ks(2)][mf(1)][lane(5)]
        int lane = idx & 31;
        int rest = idx >> 5;
        int mf = rest & 1;
        int ks = (rest >> 1) & 3;
        int ws = (rest >> 3) & 3;
        int bt = rest >> 5;
        int b0 = bt * 128 + ws * 32 + mf * 16 + (lane >> 2);
        int k0 = ks * 16 + (lane & 3) * 2;
        const float* p = in + b0 * F_DIM + k0;
        float2 v0 = *(const float2*)p;                   // a0: (b0,   k0)
        float2 v1 = *(const float2*)(p + 8 * F_DIM);     // a1: (b0+8, k0)
        float2 v2 = *(const float2*)(p + 8);             // a2: (b0,   k0+8)
        float2 v3 = *(const float2*)(p + 8 * F_DIM + 8); // a3: (b0+8, k0+8)
        uint4 o;
        o.x = packh2(v0.x, v0.y);
        o.y = packh2(v1.x, v1.y);
        o.z = packh2(v2.x, v2.y);
        o.w = packh2(v3.x, v3.y);
        g_Afrag[idx] = o;
    } else if (idx < PREP_THREADS) {
        int j = idx - AFRAG_U4;
        int x = j / (NYP * 16);
        int rem = j - x * (NYP * 16);
        int y = rem >> 4;
        int c4 = rem & 15;
        uint2 pack = {0u, 0u};
        if (y < NY) {
            float4 v = *(const float4*)(W + ((size_t)(y * NX + x) * F_DIM + c4 * 4));
            pack.x = packh2(v.x, v.y);
            pack.y = packh2(v.z, v.w);
        }
        *(uint2*)(g_Wp + ((size_t)(x * NYP + y) * KP + c4 * 4)) = pack;
    }
}

// ---------------- GEMM kernel ----------------
// Grid: (x = 0..81, by = 0..15). Block: 256 threads (8 warps, 4M x 2N).
// A fragments come straight from gmem (LDG.128); only W lives in smem.
__global__ __launch_bounds__(256, 3)
void gemm_kernel(const float* __restrict__ bias, float* __restrict__ out) {
    extern __shared__ __align__(16) char smem[];
    __half* Ws = (__half*)(smem + OFF_W);        // [96][72]
    float* Ds = (float*)(smem + OFF_DS);         // [128][68] staging
    float* bias_s = (float*)(smem + OFF_BIAS);   // [96], zero-padded

    const int x  = blockIdx.x;
    const int by = blockIdx.y;
    const int tid = threadIdx.x;
    const int lane = tid & 31;
    const int warp = tid >> 5;
    const int warpM = warp & 3;   // 0..3
    const int warpN = warp >> 2;  // 0..1
    const uint32_t sbase = smem_u32(smem);

    // ---- Prologue: W tile via cp.async + bias ----
    {
        const char* srcW = (const char*)(g_Wp + (size_t)x * NYP * KP);
        #pragma unroll
        for (int i = tid; i < NYP * 8; i += 256) {
            int r = i >> 3;
            int c = i & 7;
            cp_async16(sbase + OFF_W + r * 144 + c * 16, srcW + r * 128 + c * 16);
        }
        asm volatile("cp.async.commit_group;" ::: "memory");
    }
    if (tid < NYP) bias_s[tid] = (tid < NY) ? bias[tid * NX + x] : 0.0f;
    asm volatile("cp.async.wait_group 0;" ::: "memory");
    __syncthreads();

    // W ldmatrix base (fixed)
    const uint32_t b_base = smem_u32(Ws + (warpN * 48 + (lane & 15)) * ROWE + (lane >> 4) * 8);
    const uint32_t NG_STRIDE = 16 * ROWE * 2;

    // d-frag output coordinates
    const int r0 = warpM * 32 + (lane >> 2);
    const int cb = warpN * 48 + (lane & 3) * 2;

    for (int t = 0; t < BT_PER_CTA; t++) {
        const int bt = by * BT_PER_CTA + t;
        const uint4* aF = g_Afrag + ((size_t)(bt * 4 + warpM) << 8) + lane;

        float d[2][6][4];
        #pragma unroll
        for (int mf = 0; mf < 2; mf++)
            #pragma unroll
            for (int nf = 0; nf < 6; nf++)
                #pragma unroll
                for (int j = 0; j < 4; j++) d[mf][nf][j] = 0.0f;

        #pragma unroll
        for (int ks = 0; ks < KSTEPS; ks++) {
            // A fragments: direct LDG.128, fragment-major layout
            uint4 a0 = aF[(ks * 2 + 0) * 32];
            uint4 a1 = aF[(ks * 2 + 1) * 32];

            uint32_t bfr[3][4];
            #pragma unroll
            for (int g = 0; g < 3; g++) {
                asm volatile("ldmatrix.sync.aligned.m8n8.x4.shared.b16 {%0,%1,%2,%3}, [%4];"
                             : "=r"(bfr[g][0]), "=r"(bfr[g][1]), "=r"(bfr[g][2]), "=r"(bfr[g][3])
                             : "r"(b_base + g * NG_STRIDE + ks * 32));
            }

            const uint32_t* am[2] = { (const uint32_t*)&a0, (const uint32_t*)&a1 };
            #pragma unroll
            for (int mf = 0; mf < 2; mf++) {
                #pragma unroll
                for (int g = 0; g < 3; g++) {
                    #pragma unroll
                    for (int h = 0; h < 2; h++) {
                        float* dd = d[mf][g * 2 + h];
                        asm volatile(
                            "mma.sync.aligned.m16n8k16.row.col.f32.f16.f16.f32 "
                            "{%0,%1,%2,%3}, {%4,%5,%6,%7}, {%8,%9}, {%0,%1,%2,%3};"
                            : "+f"(dd[0]), "+f"(dd[1]), "+f"(dd[2]), "+f"(dd[3])
                            : "r"(am[mf][0]), "r"(am[mf][1]), "r"(am[mf][2]), "r"(am[mf][3]),
                              "r"(bfr[g][h]), "r"(bfr[g][2 + h]));
                    }
                }
            }
        }

        // ---- Stage to SMEM with bias folded (float2 stores) ----
        // (Ds is free: previous tile's writeout finished at loop-end sync)
        #pragma unroll
        for (int nf = 0; nf < 6; nf++) {
            const int y = cb + nf * 8;   // even
            const float b0 = bias_s[y];
            const float b1 = bias_s[y + 1];
            #pragma unroll
            for (int mf = 0; mf < 2; mf++) {
                const int rA = r0 + mf * 16;
                if (y + 1 < NY) {
                    *(float2*)&Ds[rA * DS_STRIDE + y] =
                        make_float2(d[mf][nf][0] + b0, d[mf][nf][1] + b1);
                    *(float2*)&Ds[(rA + 8) * DS_STRIDE + y] =
                        make_float2(d[mf][nf][2] + b0, d[mf][nf][3] + b1);
                } else if (y < NY) {
                    Ds[rA * DS_STRIDE + y]       = d[mf][nf][0] + b0;
                    Ds[(rA + 8) * DS_STRIDE + y] = d[mf][nf][2] + b0;
                }
            }
        }
        __syncthreads();

        // ---- Coalesced writeout: warp = 16 rows, lane = col, increments only ----
        {
            float* gRow = out + (size_t)(bt * TILE_M + warp * 16) * P_TOTAL + x * NY + lane;
            const float* sRow = Ds + (warp * 16) * DS_STRIDE + lane;
            #pragma unroll
            for (int rr = 0; rr < 16; rr++) {
                float v0 = sRow[0];
                float v1 = sRow[32];
                gRow[0]  = v0;
                gRow[32] = v1;
                if (lane < 3) gRow[64] = sRow[64];
                sRow += DS_STRIDE;
                gRow += P_TOTAL;
            }
        }
        __syncthreads();   // Ds reusable for next tile's staging
    }
}

// ---------------- Launch ----------------
extern "C" void kernel_launch(void* const* d_in, const int* in_sizes, int n_in,
                              void* d_out, int out_size) {
    const float* inputs = nullptr;  // 8192*64
    const float* W = nullptr;       // 5494*64
    const float* bias = nullptr;    // 5494
    for (int i = 0; i < n_in; i++) {
        if (in_sizes[i] == B_TOTAL * F_DIM) inputs = (const float*)d_in[i];
        else if (in_sizes[i] == P_TOTAL * F_DIM) W = (const float*)d_in[i];
        else if (in_sizes[i] == P_TOTAL) bias = (const float*)d_in[i];
    }
    float* out = (float*)d_out;

    prep_kernel<<<PREP_BLOCKS, 256>>>(inputs, W);

    cudaFuncSetAttribute(gemm_kernel, cudaFuncAttributeMaxDynamicSharedMemorySize, SMEM_TOTAL);
    dim3 grid(NX, GRID_Y);   // (82, 16)
    gemm_kernel<<<grid, 256, SMEM_TOTAL>>>(bias, out);
}

// round 7
// speedup vs baseline: 3.2335x; 1.0666x over previous
#include <cuda_runtime.h>
#include <cuda_fp16.h>
#include <cstdint>

// ---------------- Problem constants ----------------
#define B_TOTAL   8192
#define F_DIM     64
#define NX        82
#define NY        67
#define NYP       96
#define P_TOTAL   (NX * NY)      // 5494
#define KP        64             // fp16 K
#define KSTEPS    (KP / 16)      // 4

// ---------------- Tile config ----------------
#define TILE_M    128
#define BT_PER_CTA 4
#define GRID_Y    (B_TOTAL / TILE_M / BT_PER_CTA)   // 16
#define ROWE      72             // W smem row stride in fp16 (144B)

// SMEM layout (bytes): W staging image overlays Ds (W is hoisted to regs after prologue)
#define OFF_W     0
#define W_BYTES   (NYP * ROWE * 2)          // 13824
#define OFF_DS    0
#define DS_STRIDE 68
#define DS_BYTES  (TILE_M * DS_STRIDE * 4)  // 34816
#define OFF_BIAS  DS_BYTES                  // 34816
#define SMEM_TOTAL (OFF_BIAS + 384)         // 35200 -> reg-limited to 2 CTAs/SM

// ---------------- Scratch (device globals; no allocation allowed) ----------------
// A in mma fragment order: [bt][warpM][ks][mf][lane] of uint4 (16B per lane-slot)
#define AFRAG_U4  (B_TOTAL * KP * 2 / 16)   // 65536 uint4
__device__ __align__(16) uint4 g_Afrag[AFRAG_U4];
__device__ __align__(16) __half g_Wp[NX * NYP * KP];   // [x][96][64]

static __device__ __forceinline__ uint32_t smem_u32(const void* p) {
    return (uint32_t)__cvta_generic_to_shared(p);
}
static __device__ __forceinline__ void cp_async16(uint32_t dst, const void* src) {
    asm volatile("cp.async.cg.shared.global [%0], [%1], 16;" :: "r"(dst), "l"(src));
}
static __device__ __forceinline__ uint32_t packh2(float a, float b) {
    __half2 h = __floats2half2_rn(a, b);
    return *(uint32_t*)&h;
}

// ---------------- Merged prep kernel ----------------
#define W_CHUNKS (NX * NYP * 16)                 // 125952
#define PREP_THREADS (AFRAG_U4 + W_CHUNKS)       // 191488
#define PREP_BLOCKS ((PREP_THREADS + 255) / 256) // 749
__global__ void prep_kernel(const float* __restrict__ in, const float* __restrict__ W) {
    int idx = blockIdx.x * 256 + threadIdx.x;
    if (idx < AFRAG_U4) {
        // decompose: [bt(6b)][ws(2)][ks(2)][mf(1)][lane(5)]
        int lane = idx & 31;
        int rest = idx >> 5;
        int mf = rest & 1;
        int ks = (rest >> 1) & 3;
        int ws = (rest >> 3) & 3;
        int bt = rest >> 5;
        int b0 = bt * 128 + ws * 32 + mf * 16 + (lane >> 2);
        int k0 = ks * 16 + (lane & 3) * 2;
        const float* p = in + b0 * F_DIM + k0;
        float2 v0 = *(const float2*)p;                   // a0: (b0,   k0)
        float2 v1 = *(const float2*)(p + 8 * F_DIM);     // a1: (b0+8, k0)
        float2 v2 = *(const float2*)(p + 8);             // a2: (b0,   k0+8)
        float2 v3 = *(const float2*)(p + 8 * F_DIM + 8); // a3: (b0+8, k0+8)
        uint4 o;
        o.x = packh2(v0.x, v0.y);
        o.y = packh2(v1.x, v1.y);
        o.z = packh2(v2.x, v2.y);
        o.w = packh2(v3.x, v3.y);
        g_Afrag[idx] = o;
    } else if (idx < PREP_THREADS) {
        int j = idx - AFRAG_U4;
        int x = j / (NYP * 16);
        int rem = j - x * (NYP * 16);
        int y = rem >> 4;
        int c4 = rem & 15;
        uint2 pack = {0u, 0u};
        if (y < NY) {
            float4 v = *(const float4*)(W + ((size_t)(y * NX + x) * F_DIM + c4 * 4));
            pack.x = packh2(v.x, v.y);
            pack.y = packh2(v.z, v.w);
        }
        *(uint2*)(g_Wp + ((size_t)(x * NYP + y) * KP + c4 * 4)) = pack;
    }
}

// ---------------- GEMM kernel ----------------
// Grid: (x = 0..81, by = 0..15). Block: 256 threads (8 warps, 4M x 2N).
// W fragments register-resident (loaded once); A straight from gmem; smem only for epilogue.
__global__ __launch_bounds__(256, 2)
void gemm_kernel(const float* __restrict__ bias, float* __restrict__ out) {
    extern __shared__ __align__(16) char smem[];
    float* Ds = (float*)(smem + OFF_DS);         // [128][68] staging (overlays W image)
    float* bias_s = (float*)(smem + OFF_BIAS);   // [96], zero-padded

    const int x  = blockIdx.x;
    const int by = blockIdx.y;
    const int tid = threadIdx.x;
    const int lane = tid & 31;
    const int warp = tid >> 5;
    const int warpM = warp & 3;   // 0..3
    const int warpN = warp >> 2;  // 0..1
    const uint32_t sbase = smem_u32(smem);

    // ---- Prologue: W tile -> smem -> registers (once per CTA) ----
    {
        const char* srcW = (const char*)(g_Wp + (size_t)x * NYP * KP);
        #pragma unroll
        for (int i = tid; i < NYP * 8; i += 256) {
            int r = i >> 3;
            int c = i & 7;
            cp_async16(sbase + OFF_W + r * 144 + c * 16, srcW + r * 128 + c * 16);
        }
        asm volatile("cp.async.commit_group;" ::: "memory");
    }
    if (tid < NYP) bias_s[tid] = (tid < NY) ? bias[tid * NX + x] : 0.0f;
    asm volatile("cp.async.wait_group 0;" ::: "memory");
    __syncthreads();

    uint32_t wreg[KSTEPS][3][4];   // all W fragments for this warp's 48-col half
    {
        const uint32_t b_base = sbase + OFF_W
            + ((warpN * 48 + (lane & 15)) * ROWE + (lane >> 4) * 8) * 2;
        const uint32_t NG_STRIDE = 16 * ROWE * 2;
        #pragma unroll
        for (int ks = 0; ks < KSTEPS; ks++) {
            #pragma unroll
            for (int g = 0; g < 3; g++) {
                asm volatile("ldmatrix.sync.aligned.m8n8.x4.shared.b16 {%0,%1,%2,%3}, [%4];"
                             : "=r"(wreg[ks][g][0]), "=r"(wreg[ks][g][1]),
                               "=r"(wreg[ks][g][2]), "=r"(wreg[ks][g][3])
                             : "r"(b_base + g * NG_STRIDE + ks * 32));
            }
        }
    }
    __syncthreads();   // W smem image now dead; Ds staging may overwrite

    // d-frag output coordinates
    const int r0 = warpM * 32 + (lane >> 2);
    const int cb = warpN * 48 + (lane & 3) * 2;

    for (int t = 0; t < BT_PER_CTA; t++) {
        const int bt = by * BT_PER_CTA + t;
        const uint4* aF = g_Afrag + ((size_t)(bt * 4 + warpM) << 8) + lane;

        float d[2][6][4];
        #pragma unroll
        for (int mf = 0; mf < 2; mf++)
            #pragma unroll
            for (int nf = 0; nf < 6; nf++)
                #pragma unroll
                for (int j = 0; j < 4; j++) d[mf][nf][j] = 0.0f;

        #pragma unroll
        for (int ks = 0; ks < KSTEPS; ks++) {
            uint4 a0 = aF[(ks * 2 + 0) * 32];
            uint4 a1 = aF[(ks * 2 + 1) * 32];
            const uint32_t* am[2] = { (const uint32_t*)&a0, (const uint32_t*)&a1 };
            #pragma unroll
            for (int mf = 0; mf < 2; mf++) {
                #pragma unroll
                for (int g = 0; g < 3; g++) {
                    #pragma unroll
                    for (int h = 0; h < 2; h++) {
                        float* dd = d[mf][g * 2 + h];
                        asm volatile(
                            "mma.sync.aligned.m16n8k16.row.col.f32.f16.f16.f32 "
                            "{%0,%1,%2,%3}, {%4,%5,%6,%7}, {%8,%9}, {%0,%1,%2,%3};"
                            : "+f"(dd[0]), "+f"(dd[1]), "+f"(dd[2]), "+f"(dd[3])
                            : "r"(am[mf][0]), "r"(am[mf][1]), "r"(am[mf][2]), "r"(am[mf][3]),
                              "r"(wreg[ks][g][h]), "r"(wreg[ks][g][2 + h]));
                    }
                }
            }
        }

        // ---- Stage to SMEM with bias folded (float2 stores) ----
        // (Ds free: prologue sync on t=0, loop-end sync otherwise)
        #pragma unroll
        for (int nf = 0; nf < 6; nf++) {
            const int y = cb + nf * 8;   // even
            const float b0 = bias_s[y];
            const float b1 = bias_s[y + 1];
            #pragma unroll
            for (int mf = 0; mf < 2; mf++) {
                const int rA = r0 + mf * 16;
                if (y + 1 < NY) {
                    *(float2*)&Ds[rA * DS_STRIDE + y] =
                        make_float2(d[mf][nf][0] + b0, d[mf][nf][1] + b1);
                    *(float2*)&Ds[(rA + 8) * DS_STRIDE + y] =
                        make_float2(d[mf][nf][2] + b0, d[mf][nf][3] + b1);
                } else if (y < NY) {
                    Ds[rA * DS_STRIDE + y]       = d[mf][nf][0] + b0;
                    Ds[(rA + 8) * DS_STRIDE + y] = d[mf][nf][2] + b0;
                }
            }
        }
        __syncthreads();

        // ---- Coalesced writeout: warp = 16 rows, lane = col, increments only ----
        {
            float* gRow = out + (size_t)(bt * TILE_M + warp * 16) * P_TOTAL + x * NY + lane;
            const float* sRow = Ds + (warp * 16) * DS_STRIDE + lane;
            #pragma unroll
            for (int rr = 0; rr < 16; rr++) {
                float v0 = sRow[0];
                float v1 = sRow[32];
                gRow[0]  = v0;
                gRow[32] = v1;
                if (lane < 3) gRow[64] = sRow[64];
                sRow += DS_STRIDE;
                gRow += P_TOTAL;
            }
        }
        __syncthreads();   // Ds reusable for next tile's staging
    }
}

// ---------------- Launch ----------------
extern "C" void kernel_launch(void* const* d_in, const int* in_sizes, int n_in,
                              void* d_out, int out_size) {
    const float* inputs = nullptr;  // 8192*64
    const float* W = nullptr;       // 5494*64
    const float* bias = nullptr;    // 5494
    for (int i = 0; i < n_in; i++) {
        if (in_sizes[i] == B_TOTAL * F_DIM) inputs = (const float*)d_in[i];
        else if (in_sizes[i] == P_TOTAL * F_DIM) W = (const float*)d_in[i];
        else if (in_sizes[i] == P_TOTAL) bias = (const float*)d_in[i];
    }
    float* out = (float*)d_out;

    prep_kernel<<<PREP_BLOCKS, 256>>>(inputs, W);

    cudaFuncSetAttribute(gemm_kernel, cudaFuncAttributeMaxDynamicSharedMemorySize, SMEM_TOTAL);
    dim3 grid(NX, GRID_Y);   // (82, 16)
    gemm_kernel<<<grid, 256, SMEM_TOTAL>>>(bias, out);
}